// round 7
// baseline (speedup 1.0000x reference)
#include <cuda_runtime.h>
#include <cuda_bf16.h>
#include <cstddef>
#include <cstdint>

#define BATCH 64
#define SEQ   2048
#define INF   256
#define HID   512
#define OUTF  256
#define MROWS (BATCH * SEQ)   // 131072

// ---------------------------------------------------------------------------
// Scratch: sanctioned __device__ globals
// ---------------------------------------------------------------------------
__device__ float g_xproj[(size_t)MROWS * HID];   // x @ W1_x + b1, row m = b*SEQ + t
__device__ float g_hall [(size_t)MROWS * HID];   // h_t, row m = b*SEQ + t

// ---------------------------------------------------------------------------
// PTX helpers
// ---------------------------------------------------------------------------
__device__ __forceinline__ uint32_t smem_u32(const void* p) {
    uint32_t a;
    asm("{ .reg .u64 t; cvta.to.shared.u64 t, %1; cvt.u32.u64 %0, t; }"
        : "=r"(a) : "l"(p));
    return a;
}
__device__ __forceinline__ uint32_t cluster_rank() {
    uint32_t r; asm("mov.u32 %0, %%cluster_ctarank;" : "=r"(r)); return r;
}
__device__ __forceinline__ uint32_t mapa_cluster(uint32_t local, uint32_t rank) {
    uint32_t r;
    asm("mapa.shared::cluster.u32 %0, %1, %2;" : "=r"(r) : "r"(local), "r"(rank));
    return r;
}
__device__ __forceinline__ void st_cluster_v4(uint32_t addr, float4 v) {
    asm volatile("st.shared::cluster.v4.f32 [%0], {%1,%2,%3,%4};"
                 :: "r"(addr), "f"(v.x), "f"(v.y), "f"(v.z), "f"(v.w));
}
__device__ __forceinline__ void cluster_sync() {
    asm volatile("barrier.cluster.arrive.aligned;" ::: "memory");
    asm volatile("barrier.cluster.wait.aligned;"   ::: "memory");
}
// Packed dual-fp32 FMA: d = a*b + d (elementwise, 2 packed floats)
__device__ __forceinline__ void ffma2(unsigned long long& d,
                                      unsigned long long a,
                                      unsigned long long b) {
    asm("fma.rn.f32x2 %0, %1, %2, %0;" : "+l"(d) : "l"(a), "l"(b));
}
__device__ __forceinline__ void fadd2(unsigned long long& d,
                                      unsigned long long a,
                                      unsigned long long b) {
    asm("add.rn.f32x2 %0, %1, %2;" : "=l"(d) : "l"(a), "l"(b));
}
__device__ __forceinline__ unsigned long long splat2(float a) {
    unsigned long long d;
    asm("mov.b64 %0, {%1, %1};" : "=l"(d) : "f"(a));
    return d;
}

// ---------------------------------------------------------------------------
// Tiled fp32 GEMM + bias using packed f32x2 over column pairs.
// C[M,N] = A[M,K] @ B[K,N] + bias[N].  BM=BN=128, BK=16, 256 thr, 8x8/thread.
// acc2[i][j2] holds (C[i][2j2], C[i][2j2+1]); b pairs are adjacent in Bs[k][n].
// ---------------------------------------------------------------------------
template<int K, int N>
__global__ void __launch_bounds__(256, 1)
gemm_bias(const float* __restrict__ A,
          const float* __restrict__ Bm,
          const float* __restrict__ bias,
          float* __restrict__ C)
{
    __shared__ float As[16][128];
    __shared__ float Bs[16][128];

    const int tid = threadIdx.x;
    const int tx  = tid & 15;
    const int ty  = tid >> 4;
    const int cm0 = blockIdx.y * 128;
    const int cn0 = blockIdx.x * 128;

    unsigned long long acc2[8][4];
#pragma unroll
    for (int i = 0; i < 8; ++i)
#pragma unroll
        for (int j = 0; j < 4; ++j) acc2[i][j] = 0ull;

    for (int k0 = 0; k0 < K; k0 += 16) {
#pragma unroll
        for (int f = 0; f < 2; ++f) {
            int linear = tid + 256 * f;
            int m  = linear >> 2;
            int kq = linear & 3;
            float4 av = *reinterpret_cast<const float4*>(
                &A[(size_t)(cm0 + m) * K + k0 + kq * 4]);
            As[kq * 4 + 0][m] = av.x;
            As[kq * 4 + 1][m] = av.y;
            As[kq * 4 + 2][m] = av.z;
            As[kq * 4 + 3][m] = av.w;
        }
#pragma unroll
        for (int f = 0; f < 2; ++f) {
            int linear = tid + 256 * f;
            int kk = linear >> 5;
            int nq = linear & 31;
            *reinterpret_cast<float4*>(&Bs[kk][nq * 4]) =
                *reinterpret_cast<const float4*>(
                    &Bm[(size_t)(k0 + kk) * N + cn0 + nq * 4]);
        }
        __syncthreads();

#pragma unroll
        for (int kk = 0; kk < 16; ++kk) {
            float a[8];
            *reinterpret_cast<float4*>(&a[0]) =
                *reinterpret_cast<const float4*>(&As[kk][ty * 8]);
            *reinterpret_cast<float4*>(&a[4]) =
                *reinterpret_cast<const float4*>(&As[kk][ty * 8 + 4]);
            unsigned long long b2[4];
            *reinterpret_cast<ulonglong2*>(&b2[0]) =
                *reinterpret_cast<const ulonglong2*>(&Bs[kk][tx * 8]);
            *reinterpret_cast<ulonglong2*>(&b2[2]) =
                *reinterpret_cast<const ulonglong2*>(&Bs[kk][tx * 8 + 4]);
#pragma unroll
            for (int i = 0; i < 8; ++i) {
                unsigned long long as = splat2(a[i]);
#pragma unroll
                for (int j = 0; j < 4; ++j)
                    ffma2(acc2[i][j], as, b2[j]);
            }
        }
        __syncthreads();
    }

    unsigned long long bv2[4];
    *reinterpret_cast<ulonglong2*>(&bv2[0]) =
        *reinterpret_cast<const ulonglong2*>(&bias[cn0 + tx * 8]);
    *reinterpret_cast<ulonglong2*>(&bv2[2]) =
        *reinterpret_cast<const ulonglong2*>(&bias[cn0 + tx * 8 + 4]);

#pragma unroll
    for (int i = 0; i < 8; ++i) {
        size_t row = (size_t)(cm0 + ty * 8 + i);
        unsigned long long o[4];
#pragma unroll
        for (int j = 0; j < 4; ++j) fadd2(o[j], acc2[i][j], bv2[j]);
        *reinterpret_cast<ulonglong2*>(&C[row * N + cn0 + tx * 8]) =
            make_ulonglong2(o[0], o[1]);
        *reinterpret_cast<ulonglong2*>(&C[row * N + cn0 + tx * 8 + 4]) =
            make_ulonglong2(o[2], o[3]);
    }
}

// ---------------------------------------------------------------------------
// Cluster-based persistent recurrent kernel (structure proven in R5).
//
// 128 CTAs = 16 row-groups (4 batch rows) x 8 col-groups (64 hidden cols);
// each row-group's 8 CTAs = one CGA cluster (rank == col group).
// SMEM: Wsm [64 cols][512 k] 128KB + h double buffer 2x(4x512) 16KB.
// k layout: lane l, phase p -> pair p*32+l; kb = 8*lane + 256*p (p=0..7).
// Warp tile 4 rows x 8 cols; W phases 0..3 cached in 64 regs.
// Butterfly: lane l ends with full sum for tile index l (row l>>3, col w*8+(l&7)).
//
// R6: float4 DSMEM push (3 shfl gather, lanes l%4==0 store v4 to 8 peers),
//     float4 STG of h, xp prefetch, h_last fused.
// ---------------------------------------------------------------------------
#define WSM_FLOATS  (64 * 512)      // 131072 B
#define HBUF_FLOATS (4 * 512)       // 8192 B per buffer
#define RNN_SMEM_BYTES ((WSM_FLOATS + 2 * HBUF_FLOATS) * 4)   // 147456

__global__ void __launch_bounds__(256, 1) __cluster_dims__(8, 1, 1)
rnn_recurrent(const float* __restrict__ W1, float* __restrict__ hlast_out)
{
    extern __shared__ float sm[];
    float* Wsm  = sm;                         // [c*512 + k]
    float* hbuf = sm + WSM_FLOATS;            // [parity][row*512 + gcol]

    const int tid   = threadIdx.x;
    const int lane  = tid & 31;
    const int w     = tid >> 5;               // warp 0..7
    const uint32_t rank = cluster_rank();     // 0..7 = col group
    const int gb    = blockIdx.x >> 3;        // 0..15 row group
    const int rb    = gb * 4;                 // batch row base
    const int cb    = (int)rank * 64;         // hidden col base

    // Load W1_h col slice: Wsm[c*512 + k] = W1[k][cb + c]
    for (int idx = tid; idx < WSM_FLOATS; idx += 256) {
        int c = idx & 63, k = idx >> 6;
        Wsm[c * 512 + k] = W1[(size_t)k * 512 + cb + c];
    }
    __syncthreads();

    // Per-thread geometry
    const int orow = lane >> 3;               // 0..3
    const int ocol = w * 8 + (lane & 7);      // 0..63 local col
    const int gcol = cb + ocol;               // global hidden col
    const size_t xp_base =
        ((size_t)(rb + orow) * SEQ) * HID + gcol;
    const int koff0 = 8 * lane;               // 0..248 bytes

    // Register cache of W for phases 0..3
    unsigned long long wc[4][8];
#pragma unroll
    for (int p = 0; p < 4; ++p)
#pragma unroll
        for (int j = 0; j < 8; ++j)
            wc[p][j] = *reinterpret_cast<const unsigned long long*>(
                reinterpret_cast<const char*>(&Wsm[(w * 8 + j) * 512]) +
                koff0 + p * 256);

    // Peer hbuf base addresses
    uint32_t hbase_local = smem_u32(hbuf);
    uint32_t peer_base[8];
#pragma unroll
    for (int pr = 0; pr < 8; ++pr)
        peer_base[pr] = mapa_cluster(hbase_local, (uint32_t)pr);
    // vector-store offset (only lanes with lane%4==0 store): 16B aligned
    const uint32_t my_off = (uint32_t)(orow * 512 + gcol) * 4u;

    float xp = __ldg(&g_xproj[xp_base]);      // t = 0

    for (int t = 0; t < SEQ; ++t) {
        // Prefetch next step's xproj early (overlaps all compute below)
        float xp_nxt = 0.0f;
        if (t + 1 < SEQ) xp_nxt = __ldg(&g_xproj[xp_base + (size_t)(t + 1) * HID]);

        float v;
        if (t == 0) {
            v = tanhf(xp);                    // h0 == 0
        } else {
            const char* hprev = reinterpret_cast<const char*>(
                hbuf + ((t & 1) ^ 1) * HBUF_FLOATS);

            unsigned long long acc[32];
#pragma unroll
            for (int a = 0; a < 32; ++a) acc[a] = 0ull;

#pragma unroll
            for (int p = 0; p < 8; ++p) {
                const int kb = koff0 + p * 256;     // 0..2040
                unsigned long long h2[4];
#pragma unroll
                for (int i = 0; i < 4; ++i)
                    h2[i] = *reinterpret_cast<const unsigned long long*>(
                        hprev + i * 2048 + kb);
                if (p < 4) {
#pragma unroll
                    for (int i = 0; i < 4; ++i)
#pragma unroll
                        for (int j = 0; j < 8; ++j)
                            ffma2(acc[i * 8 + j], h2[i], wc[p][j]);
                } else {
                    unsigned long long w2[8];
#pragma unroll
                    for (int j = 0; j < 8; ++j)
                        w2[j] = *reinterpret_cast<const unsigned long long*>(
                            reinterpret_cast<const char*>(&Wsm[(w * 8 + j) * 512]) + kb);
#pragma unroll
                    for (int i = 0; i < 4; ++i)
#pragma unroll
                        for (int j = 0; j < 8; ++j)
                            ffma2(acc[i * 8 + j], h2[i], w2[j]);
                }
            }

            // Collapse f32x2 halves -> 32 scalars
            float s[32];
#pragma unroll
            for (int a = 0; a < 32; ++a) {
                float2 f = *reinterpret_cast<float2*>(&acc[a]);
                s[a] = f.x + f.y;
            }

            // Compacting butterfly: lane l ends with full sum for index l
#pragma unroll
            for (int off = 16; off > 0; off >>= 1) {
                bool up = (lane & off) != 0;
#pragma unroll
                for (int a = 0; a < 16; ++a) {
                    if (a >= off) continue;
                    float send = up ? s[a] : s[a + off];
                    float recv = __shfl_xor_sync(0xffffffffu, send, off);
                    float keep = up ? s[a + off] : s[a];
                    s[a] = keep + recv;
                }
            }
            v = tanhf(s[0] + xp);
        }

        // Gather float4 within each aligned 4-lane group (cols 4-aligned, same row)
        float v1 = __shfl_down_sync(0xffffffffu, v, 1);
        float v2 = __shfl_down_sync(0xffffffffu, v, 2);
        float v3 = __shfl_down_sync(0xffffffffu, v, 3);

        if ((lane & 3) == 0) {
            float4 vv = make_float4(v, v1, v2, v3);
            // h_t for the post-GEMM (STG.128, full sectors)
            *reinterpret_cast<float4*>(&g_hall[xp_base + (size_t)t * HID]) = vv;
            if (t == SEQ - 1)
                *reinterpret_cast<float4*>(
                    &hlast_out[(size_t)(rb + orow) * HID + gcol]) = vv;
            // push to all 8 cluster CTAs' buffer (t&1)
            const uint32_t doff =
                (uint32_t)((t & 1) * (HBUF_FLOATS * 4)) + my_off;
#pragma unroll
            for (int pr = 0; pr < 8; ++pr)
                st_cluster_v4(peer_base[pr] + doff, vv);
        }

        // One cluster barrier per step (release pushes / acquire for reads;
        // double buffer handles WAR across adjacent steps)
        cluster_sync();

        xp = xp_nxt;
    }
}

// ---------------------------------------------------------------------------
// Launch
// ---------------------------------------------------------------------------
extern "C" void kernel_launch(void* const* d_in, const int* in_sizes, int n_in,
                              void* d_out, int out_size)
{
    const float* x  = (const float*)d_in[0];   // (64, 2048, 256)
    const float* W1 = (const float*)d_in[1];   // (768, 512): [0:512]=W1_h, [512:768]=W1_x
    const float* b1 = (const float*)d_in[2];   // (512,)
    const float* W2 = (const float*)d_in[3];   // (512, 256)
    const float* b2 = (const float*)d_in[4];   // (256,)
    float* out = (float*)d_out;

    float* xproj = nullptr;
    float* hall  = nullptr;
    cudaGetSymbolAddress((void**)&xproj, g_xproj);
    cudaGetSymbolAddress((void**)&hall,  g_hall);

    cudaFuncSetAttribute(rnn_recurrent,
                         cudaFuncAttributeMaxDynamicSharedMemorySize,
                         RNN_SMEM_BYTES);

    // 1) xproj = x @ W1_x + b1   (M=131072, K=256, N=512)
    {
        dim3 grid(HID / 128, MROWS / 128);
        gemm_bias<INF, HID><<<grid, 256>>>(x, W1 + (size_t)HID * HID, b1, xproj);
    }

    // 2) recurrence: h_t = tanh(h_{t-1} @ W1_h + xproj_t); h_last -> out tail
    {
        float* hlast_out = out + ((size_t)out_size - (size_t)BATCH * HID);
        rnn_recurrent<<<128, 256, RNN_SMEM_BYTES>>>(W1, hlast_out);
    }

    // 3) output = hall @ W2 + b2  (M=131072, K=512, N=256)
    {
        dim3 grid(OUTF / 128, MROWS / 128);
        gemm_bias<HID, OUTF><<<grid, 256>>>(hall, W2, b2, out);
    }
}